// round 8
// baseline (speedup 1.0000x reference)
#include <cuda_runtime.h>
#include <cuda_fp16.h>
#include <cstdint>
#include <cstddef>

#define B_  4
#define S_  2048
#define D_  512
#define H_  8
#define DEPTH 64
#define BH  (B_*H_)

// ---------------- scratch (no allocations allowed) ----------------
__device__ float g_Q[(size_t)BH*S_*DEPTH];    // Q'  head-split (bh, s, d)
__device__ float g_K[(size_t)BH*S_*DEPTH];    // K'' = k@Wk + pos@Wd (head-split)
__device__ float g_V[(size_t)BH*S_*DEPTH];    // V'  head-split
__device__ float g_ctx[(size_t)B_*S_*D_];     // ctx in (B,S,D) layout
__device__ float g_rsinv[(size_t)BH*S_];      // 1/rowsum
__device__ __half g_E[(size_t)BH*S_*S_];      // unnormalized exp(logits/8), fp16

// ---------------- tf32 helpers ----------------
__device__ __forceinline__ uint32_t f2tf(float x){
    uint32_t u; asm("cvt.rna.tf32.f32 %0, %1;" : "=r"(u) : "f"(x)); return u;
}
__device__ __forceinline__ uint4 tf4(float4 v){
    return make_uint4(f2tf(v.x), f2tf(v.y), f2tf(v.z), f2tf(v.w));
}
__device__ __forceinline__ void mma8(float c[4], uint32_t a0,uint32_t a1,uint32_t a2,uint32_t a3,
                                     uint32_t b0,uint32_t b1){
    asm volatile("mma.sync.aligned.m16n8k8.row.col.f32.tf32.tf32.f32 "
        "{%0,%1,%2,%3}, {%4,%5,%6,%7}, {%8,%9}, {%0,%1,%2,%3};"
        : "+f"(c[0]),"+f"(c[1]),"+f"(c[2]),"+f"(c[3])
        : "r"(a0),"r"(a1),"r"(a2),"r"(a3),"r"(b0),"r"(b1));
}

// ---------------- shared GEMM core (projections / output proj) ----------------
__device__ __forceinline__ void gemm_core(
    const float* __restrict__ A1, const float* __restrict__ B1, const float* __restrict__ bias1,
    const float* __restrict__ A2, const float* __restrict__ B2, const float* __restrict__ bias2,
    float* __restrict__ C, int split, int m0, int n0,
    uint32_t (*As)[36], uint32_t (*Bs)[72])
{
    int tid = threadIdx.x;
    int lane = tid & 31, wid = tid >> 5;
    int g = lane >> 2, tg = lane & 3;
    int wm = wid & 3, wn = wid >> 2;          // 4x2 warps -> CTA tile 128x64

    float acc[2][4][4];
    #pragma unroll
    for (int i=0;i<2;i++)
        #pragma unroll
        for (int j=0;j<4;j++)
            #pragma unroll
            for (int r=0;r<4;r++) acc[i][j][r]=0.f;

    const int ntile = A2 ? 32 : 16;
    float4 ra[4]; float4 rb[2];
    auto ldg_tile = [&](int t){
        const float* A  = (t >= 16) ? A2 : A1;
        const float* Bm = (t >= 16) ? B2 : B1;
        int k0 = (t & 15) * 32;
        #pragma unroll
        for (int i=0;i<4;i++){
            int e = tid + i*256; int r = e>>3, c = (e&7)*4;
            ra[i] = *(const float4*)(A + (size_t)(m0+r)*512 + k0 + c);
        }
        #pragma unroll
        for (int i=0;i<2;i++){
            int e = tid + i*256; int r = e>>4, c = (e&15)*4;
            rb[i] = *(const float4*)(Bm + (size_t)(k0+r)*512 + n0 + c);
        }
    };

    ldg_tile(0);
    for (int t = 0; t < ntile; t++){
        #pragma unroll
        for (int i=0;i<4;i++){
            int e = tid + i*256; int r = e>>3, c = (e&7)*4;
            *(uint4*)&As[r][c] = tf4(ra[i]);
        }
        #pragma unroll
        for (int i=0;i<2;i++){
            int e = tid + i*256; int r = e>>4, c = (e&15)*4;
            *(uint4*)&Bs[r][c] = tf4(rb[i]);
        }
        __syncthreads();
        if (t+1 < ntile) ldg_tile(t+1);
        #pragma unroll
        for (int kk=0; kk<32; kk+=8){
            uint32_t af[2][4];
            #pragma unroll
            for (int mi=0;mi<2;mi++){
                int rb_ = wm*32 + mi*16;
                af[mi][0]=As[rb_+g  ][kk+tg  ];
                af[mi][1]=As[rb_+g+8][kk+tg  ];
                af[mi][2]=As[rb_+g  ][kk+tg+4];
                af[mi][3]=As[rb_+g+8][kk+tg+4];
            }
            #pragma unroll
            for (int ni=0;ni<4;ni++){
                int cb = wn*32 + ni*8 + g;
                uint32_t b0=Bs[kk+tg  ][cb];
                uint32_t b1=Bs[kk+tg+4][cb];
                mma8(acc[0][ni], af[0][0],af[0][1],af[0][2],af[0][3], b0,b1);
                mma8(acc[1][ni], af[1][0],af[1][1],af[1][2],af[1][3], b0,b1);
            }
        }
        __syncthreads();
    }

    #pragma unroll
    for (int mi=0;mi<2;mi++)
        #pragma unroll
        for (int ni=0;ni<4;ni++)
            #pragma unroll
            for (int half=0; half<2; half++){
                int row = m0 + wm*32 + mi*16 + g + half*8;
                int col = n0 + wn*32 + ni*8 + tg*2;
                float b0v = bias1[col]   + (bias2 ? bias2[col]   : 0.f);
                float b1v = bias1[col+1] + (bias2 ? bias2[col+1] : 0.f);
                float v0 = acc[mi][ni][half*2+0] + b0v;
                float v1 = acc[mi][ni][half*2+1] + b1v;
                size_t idx;
                if (split){
                    int b = row >> 11, s = row & 2047;
                    int h = col >> 6,  d = col & 63;
                    idx = (((size_t)(b*H_ + h))*S_ + s)*DEPTH + d;
                } else {
                    idx = (size_t)row*512 + col;
                }
                *(float2*)(C + idx) = make_float2(v0, v1);
            }
}

// z=0: Q'=q@Wq+bq   z=1: K''=k@Wk+pe@Wd+bk+bd   z=2: V'=v@Wv+bv
__global__ __launch_bounds__(256)
void proj3(const float* q, const float* k, const float* pe, const float* v,
           const float* Wq, const float* Wk, const float* Wv, const float* Wd,
           const float* bq, const float* bk, const float* bv, const float* bd,
           float* Qp, float* Kp, float* Vp)
{
    __shared__ uint32_t As[128][36];
    __shared__ uint32_t Bs[32][72];
    int m0 = blockIdx.y*128, n0 = blockIdx.x*64;
    if (blockIdx.z == 0)
        gemm_core(q, Wq, bq, nullptr,nullptr,nullptr, Qp, 1, m0,n0, As,Bs);
    else if (blockIdx.z == 1)
        gemm_core(k, Wk, bk, pe, Wd, bd, Kp, 1, m0,n0, As,Bs);
    else
        gemm_core(v, Wv, bv, nullptr,nullptr,nullptr, Vp, 1, m0,n0, As,Bs);
}

__global__ __launch_bounds__(256)
void gemm_out(const float* __restrict__ A, const float* __restrict__ Bm,
              const float* __restrict__ bias, float* __restrict__ C)
{
    __shared__ uint32_t As[128][36];
    __shared__ uint32_t Bs[32][72];
    gemm_core(A, Bm, bias, nullptr,nullptr,nullptr, C, 0,
              blockIdx.y*128, blockIdx.x*64, As, Bs);
}

// ---------------- pass 1: QK once -> E fp16 + rowsum ----------------
__global__ __launch_bounds__(256)
void attn_qk(const float* __restrict__ Q, const float* __restrict__ Kp,
             float* __restrict__ rsinv)
{
    extern __shared__ uint32_t sm1[];
    uint32_t (*Qs)[68] = (uint32_t(*)[68])sm1;                 // 128x68 tf32
    uint32_t (*Ks)[68] = (uint32_t(*)[68])(sm1 + 128*68);      // 64x68 tf32
    float *rs = (float*)(sm1 + 128*68 + 64*68);                // 128

    int tid = threadIdx.x;
    int lane = tid & 31, wid = tid >> 5;
    int g = lane >> 2, tg = lane & 3;
    int wm = wid & 3, wn = wid >> 2;
    int bh = blockIdx.y;
    int s0 = blockIdx.x * 128;

    const float* Qb = Q  + ((size_t)bh*S_ + s0)*DEPTH;
    const float* Kb = Kp +  (size_t)bh*S_*DEPTH;
    __half* Eb = g_E + ((size_t)bh*S_ + s0)*S_;

    #pragma unroll
    for (int i=0;i<8;i++){
        int e = tid + i*256;
        int r = e>>4, c = (e&15)*4;
        float4 v = *(const float4*)(Qb + (size_t)r*DEPTH + c);
        *(uint4*)&Qs[r][c] = tf4(v);
    }
    if (tid < 128) rs[tid] = 0.f;
    __syncthreads();

    float4 kr[4];
    auto ldgK = [&](int t0){
        #pragma unroll
        for (int i=0;i<4;i++){
            int e = tid + i*256;
            int r = e>>4, c = (e&15)*4;
            kr[i] = *(const float4*)(Kb + (size_t)(t0+r)*DEPTH + c);
        }
    };
    ldgK(0);

    float rowacc[4] = {0.f,0.f,0.f,0.f};

    for (int t0 = 0; t0 < S_; t0 += 64){
        #pragma unroll
        for (int i=0;i<4;i++){
            int e = tid + i*256;
            int r = e>>4, c = (e&15)*4;
            *(uint4*)&Ks[r][c] = tf4(kr[i]);
        }
        __syncthreads();
        if (t0 + 64 < S_) ldgK(t0 + 64);

        float acc[2][4][4];
        #pragma unroll
        for (int i=0;i<2;i++)
            #pragma unroll
            for (int j=0;j<4;j++)
                #pragma unroll
                for (int r=0;r<4;r++) acc[i][j][r]=0.f;

        #pragma unroll
        for (int kk=0; kk<64; kk+=8){
            uint32_t af[2][4];
            #pragma unroll
            for (int mi=0;mi<2;mi++){
                int rb = wm*32 + mi*16;
                af[mi][0]=Qs[rb+g  ][kk+tg  ];
                af[mi][1]=Qs[rb+g+8][kk+tg  ];
                af[mi][2]=Qs[rb+g  ][kk+tg+4];
                af[mi][3]=Qs[rb+g+8][kk+tg+4];
            }
            #pragma unroll
            for (int ni=0;ni<4;ni++){
                int cb = wn*32 + ni*8 + g;        // t index
                uint32_t b0=Ks[cb][kk+tg  ];
                uint32_t b1=Ks[cb][kk+tg+4];
                mma8(acc[0][ni], af[0][0],af[0][1],af[0][2],af[0][3], b0,b1);
                mma8(acc[1][ni], af[1][0],af[1][1],af[1][2],af[1][3], b0,b1);
            }
        }

        // E = exp(l/8); accumulate rowsums; store E fp16
        #pragma unroll
        for (int mi=0;mi<2;mi++)
            #pragma unroll
            for (int ni=0;ni<4;ni++){
                #pragma unroll
                for (int r2=0;r2<4;r2++){
                    float e_ = __expf(acc[mi][ni][r2]*0.125f);
                    acc[mi][ni][r2] = e_;
                    rowacc[mi*2 + (r2>>1)] += e_;
                }
                #pragma unroll
                for (int half=0; half<2; half++){
                    int rloc = wm*32 + mi*16 + g + half*8;
                    int cloc = wn*32 + ni*8 + tg*2;
                    *(__half2*)(Eb + (size_t)rloc*S_ + t0 + cloc) =
                        __floats2half2_rn(acc[mi][ni][half*2], acc[mi][ni][half*2+1]);
                }
            }
        __syncthreads();   // before Ks is overwritten
    }

    #pragma unroll
    for (int i=0;i<4;i++){
        float v = rowacc[i];
        v += __shfl_xor_sync(0xffffffffu, v, 1);
        v += __shfl_xor_sync(0xffffffffu, v, 2);
        if (tg == 0){
            int row = wm*32 + (i>>1)*16 + g + (i&1)*8;
            atomicAdd(&rs[row], v);
        }
    }
    __syncthreads();
    if (tid < 128) rsinv[(size_t)bh*S_ + s0 + tid] = 1.0f / rs[tid];
}

// ---------------- pass 2: normalize E -> attn, PV GEMM -> ctx ----------------
__global__ __launch_bounds__(256, 3)
void attn_pv2(const float* __restrict__ V, const float* __restrict__ rsinv,
              float* __restrict__ attn, float* __restrict__ ctx)
{
    extern __shared__ uint32_t sm2[];
    uint32_t (*Ps)[68] = (uint32_t(*)[68])sm2;                  // 128x68 tf32
    uint32_t (*Vs)[72] = (uint32_t(*)[72])(sm2 + 128*68);       // 64x72 tf32
    float *rsv = (float*)(sm2 + 128*68 + 64*72);                // 128

    int tid = threadIdx.x;
    int lane = tid & 31, wid = tid >> 5;
    int g = lane >> 2, tg = lane & 3;
    int wm = wid & 3, wn = wid >> 2;
    int bh = blockIdx.y;
    int s0 = blockIdx.x * 128;

    const float* Vb = V + (size_t)bh*S_*DEPTH;
    const __half* Eb = g_E + ((size_t)bh*S_ + s0)*S_;
    float* attn_strip = attn + ((size_t)bh*S_ + s0)*S_;

    if (tid < 128) rsv[tid] = rsinv[(size_t)bh*S_ + s0 + tid];
    __syncthreads();

    float4 vr[4];
    auto ldgV = [&](int t0){
        #pragma unroll
        for (int i=0;i<4;i++){
            int e = tid + i*256;
            int r = e>>4, c = (e&15)*4;
            vr[i] = *(const float4*)(Vb + (size_t)(t0+r)*DEPTH + c);
        }
    };
    ldgV(0);

    float octx[2][4][4];
    #pragma unroll
    for (int i=0;i<2;i++)
        #pragma unroll
        for (int j=0;j<4;j++)
            #pragma unroll
            for (int r=0;r<4;r++) octx[i][j][r]=0.f;

    for (int t0 = 0; t0 < S_; t0 += 64){
        // stage V tile
        #pragma unroll
        for (int i=0;i<4;i++){
            int e = tid + i*256;
            int r = e>>4, c = (e&15)*4;
            *(uint4*)&Vs[r][c] = tf4(vr[i]);
        }
        // load E frag, normalize, write attn, stage P (tf32)
        #pragma unroll
        for (int mi=0;mi<2;mi++){
            int r0 = wm*32 + mi*16 + g;
            float inv0 = rsv[r0], inv1 = rsv[r0+8];
            #pragma unroll
            for (int ni=0;ni<4;ni++)
                #pragma unroll
                for (int half=0; half<2; half++){
                    int rloc = r0 + half*8;
                    int cloc = wn*32 + ni*8 + tg*2;
                    float inv = half ? inv1 : inv0;
                    __half2 ev = *(const __half2*)(Eb + (size_t)rloc*S_ + t0 + cloc);
                    float2 v2 = make_float2(__half2float(ev.x)*inv, __half2float(ev.y)*inv);
                    *(uint2*)&Ps[rloc][cloc] = make_uint2(f2tf(v2.x), f2tf(v2.y));
                    *(float2*)(attn_strip + (size_t)rloc*S_ + t0 + cloc) = v2;
                }
        }
        __syncthreads();   // P,V staged
        if (t0 + 64 < S_) ldgV(t0 + 64);

        // ctx += P @ V
        #pragma unroll
        for (int kk=0; kk<64; kk+=8){
            uint32_t af[2][4];
            #pragma unroll
            for (int mi=0;mi<2;mi++){
                int rb = wm*32 + mi*16;
                af[mi][0]=Ps[rb+g  ][kk+tg  ];
                af[mi][1]=Ps[rb+g+8][kk+tg  ];
                af[mi][2]=Ps[rb+g  ][kk+tg+4];
                af[mi][3]=Ps[rb+g+8][kk+tg+4];
            }
            #pragma unroll
            for (int ni=0;ni<4;ni++){
                int cb = wn*32 + ni*8 + g;       // d index
                uint32_t b0=Vs[kk+tg  ][cb];
                uint32_t b1=Vs[kk+tg+4][cb];
                mma8(octx[0][ni], af[0][0],af[0][1],af[0][2],af[0][3], b0,b1);
                mma8(octx[1][ni], af[1][0],af[1][1],af[1][2],af[1][3], b0,b1);
            }
        }
        __syncthreads();   // before Ps/Vs overwritten next iter
    }

    // write ctx in (B,S,D) layout
    int b = bh >> 3, h = bh & 7;
    #pragma unroll
    for (int mi=0;mi<2;mi++)
        #pragma unroll
        for (int ni=0;ni<4;ni++)
            #pragma unroll
            for (int half=0; half<2; half++){
                int row = s0 + wm*32 + mi*16 + g + half*8;
                int col = h*64 + wn*32 + ni*8 + tg*2;
                float2 v2 = make_float2(octx[mi][ni][half*2], octx[mi][ni][half*2+1]);
                *(float2*)(ctx + ((size_t)b*S_ + row)*D_ + col) = v2;
            }
}

// ---------------- launch ----------------
extern "C" void kernel_launch(void* const* d_in, const int* in_sizes, int n_in,
                              void* d_out, int out_size)
{
    const float* q   = (const float*)d_in[0];
    const float* k   = (const float*)d_in[1];
    const float* v   = (const float*)d_in[2];
    const float* pe  = (const float*)d_in[3];
    // d_in[4] = mask (unused by reference)
    const float* Wq  = (const float*)d_in[5];
    const float* bq  = (const float*)d_in[6];
    const float* Wk  = (const float*)d_in[7];
    const float* bk  = (const float*)d_in[8];
    const float* Wv  = (const float*)d_in[9];
    const float* bv  = (const float*)d_in[10];
    const float* Wd  = (const float*)d_in[11];
    const float* bd  = (const float*)d_in[12];

    float* out  = (float*)d_out;                       // (B,S,D)
    float* attn = out + (size_t)B_*S_*D_;              // (B,H,S,S)

    float *Qp, *Kp, *Vp, *Ctx, *Rs;
    cudaGetSymbolAddress((void**)&Qp,  g_Q);
    cudaGetSymbolAddress((void**)&Kp,  g_K);
    cudaGetSymbolAddress((void**)&Vp,  g_V);
    cudaGetSymbolAddress((void**)&Ctx, g_ctx);
    cudaGetSymbolAddress((void**)&Rs,  g_rsinv);

    // Q', K''(=k@Wk+pe@Wd), V' in one launch
    proj3<<<dim3(8, 64, 3), 256>>>(q, k, pe, v, Wq, Wk, Wv, Wd,
                                   bq, bk, bv, bd, Qp, Kp, Vp);

    size_t smA = (size_t)(128*68 + 64*68 + 128) * sizeof(uint32_t);
    cudaFuncSetAttribute(attn_qk, cudaFuncAttributeMaxDynamicSharedMemorySize, (int)smA);
    attn_qk<<<dim3(16, BH), 256, smA>>>(Qp, Kp, Rs);

    size_t smB = (size_t)(128*68 + 64*72 + 128) * sizeof(uint32_t);
    cudaFuncSetAttribute(attn_pv2, cudaFuncAttributeMaxDynamicSharedMemorySize, (int)smB);
    attn_pv2<<<dim3(16, BH), 256, smB>>>(Vp, Rs, attn, Ctx);

    gemm_out<<<dim3(8, 64), 256>>>(Ctx, Wd, bd, out);
}

// round 9
// speedup vs baseline: 1.9542x; 1.9542x over previous
#include <cuda_runtime.h>
#include <cuda_fp16.h>
#include <cstdint>
#include <cstddef>

#define B_  4
#define S_  2048
#define D_  512
#define H_  8
#define DEPTH 64
#define BH  (B_*H_)

// ---------------- scratch (no allocations allowed) ----------------
__device__ __half g_WT[(size_t)4*512*512];      // W^T fp16 [which][n][k]
__device__ __half g_Qh[(size_t)BH*S_*DEPTH];    // Q'  fp16 head-split (bh,s,d)
__device__ __half g_Kh[(size_t)BH*S_*DEPTH];    // K'' fp16 head-split
__device__ __half g_Vh[(size_t)BH*S_*DEPTH];    // V'  fp16 head-split
__device__ __half g_Vt[(size_t)BH*DEPTH*S_];    // V'^T fp16 (bh,d,t)
__device__ float  g_ctx[(size_t)B_*S_*D_];      // ctx fp32 (B,S,D)
__device__ float  g_rsinv[(size_t)BH*S_];       // 1/rowsum

// ---------------- fp16 helpers ----------------
__device__ __forceinline__ uint32_t pack2(float a, float b){
    __half2 h = __floats2half2_rn(a, b);
    return *(uint32_t*)&h;
}
__device__ __forceinline__ void mma16(float c[4], uint32_t a0,uint32_t a1,uint32_t a2,uint32_t a3,
                                      uint32_t b0,uint32_t b1){
    asm volatile("mma.sync.aligned.m16n8k16.row.col.f32.f16.f16.f32 "
        "{%0,%1,%2,%3}, {%4,%5,%6,%7}, {%8,%9}, {%0,%1,%2,%3};"
        : "+f"(c[0]),"+f"(c[1]),"+f"(c[2]),"+f"(c[3])
        : "r"(a0),"r"(a1),"r"(a2),"r"(a3),"r"(b0),"r"(b1));
}

// ---------------- W transpose + fp16 convert ----------------
__global__ __launch_bounds__(256)
void transW(const float* Wq, const float* Wk, const float* Wv, const float* Wd)
{
    __shared__ float ts[64][65];
    const float* W = (blockIdx.z==0)?Wq:(blockIdx.z==1)?Wk:(blockIdx.z==2)?Wv:Wd;
    __half* WT = g_WT + (size_t)blockIdx.z*512*512;
    int k0 = blockIdx.y*64, n0 = blockIdx.x*64;
    int tid = threadIdx.x;
    #pragma unroll
    for (int i=0;i<4;i++){
        int e = tid + i*256;
        int r = e>>4, c = (e&15)*4;     // r = k, c = n
        float4 x = *(const float4*)(W + (size_t)(k0+r)*512 + n0 + c);
        ts[r][c]=x.x; ts[r][c+1]=x.y; ts[r][c+2]=x.z; ts[r][c+3]=x.w;
    }
    __syncthreads();
    #pragma unroll
    for (int i=0;i<2;i++){
        int u = tid + i*256;
        int n = u>>3, seg = (u&7)*8;    // 8 k halves
        uint32_t h[4];
        #pragma unroll
        for (int j=0;j<4;j++)
            h[j] = pack2(ts[seg+2*j][n], ts[seg+2*j+1][n]);
        *(uint4*)(WT + (size_t)(n0+n)*512 + k0 + seg) = make_uint4(h[0],h[1],h[2],h[3]);
    }
}

// ---------------- V transpose (fp16 -> fp16, per head) ----------------
__global__ __launch_bounds__(256)
void transV()
{
    __shared__ __half ts[64][72];
    int tid = threadIdx.x;
    int bh = blockIdx.y, t0 = blockIdx.x*64;
    const __half* src = g_Vh + ((size_t)bh*S_ + t0)*DEPTH;
    #pragma unroll
    for (int i=0;i<2;i++){
        int u = tid + i*256;
        int r = u>>3, c = (u&7)*8;
        *(uint4*)&ts[r][c] = *(const uint4*)(src + (size_t)r*DEPTH + c);
    }
    __syncthreads();
    #pragma unroll
    for (int i=0;i<2;i++){
        int u = tid + i*256;
        int d = u>>3, seg = (u&7)*8;
        __half h[8];
        #pragma unroll
        for (int j=0;j<8;j++) h[j] = ts[seg+j][d];
        *(uint4*)(g_Vt + ((size_t)bh*DEPTH + d)*S_ + t0 + seg) = *(uint4*)h;
    }
}

// ---------------- fp16 GEMM core: C = A@W^T(+A2@W2^T) + bias ----------------
// As[128][20] (16 k-pairs + pad), Bs[64][20]. HALF_OUT: head-split fp16, else fp32 row-major.
template<int HALF_OUT>
__device__ __forceinline__ void gemm16_core(
    const float* __restrict__ A1, const __half* __restrict__ BT1, const float* __restrict__ bias1,
    const float* __restrict__ A2, const __half* __restrict__ BT2, const float* __restrict__ bias2,
    float* __restrict__ Cf, __half* __restrict__ Ch, int m0, int n0,
    uint32_t (*As)[20], uint32_t (*Bs)[20])
{
    int tid = threadIdx.x;
    int lane = tid & 31, wid = tid >> 5;
    int g = lane >> 2, tg = lane & 3;
    int wm = wid & 3, wn = wid >> 2;          // 4x2 warps -> CTA tile 128x64

    float acc[2][4][4];
    #pragma unroll
    for (int i=0;i<2;i++)
        #pragma unroll
        for (int j=0;j<4;j++)
            #pragma unroll
            for (int r=0;r<4;r++) acc[i][j][r]=0.f;

    const int ntile = A2 ? 32 : 16;
    float4 ra[4]; uint4 rbh;
    auto ldg_tile = [&](int t){
        const float* A   = (t >= 16) ? A2  : A1;
        const __half* BT = (t >= 16) ? BT2 : BT1;
        int k0 = (t & 15) * 32;
        #pragma unroll
        for (int i=0;i<4;i++){
            int e = tid + i*256; int r = e>>3, c = (e&7)*4;
            ra[i] = *(const float4*)(A + (size_t)(m0+r)*512 + k0 + c);
        }
        rbh = *(const uint4*)(BT + (size_t)(n0 + (tid>>2))*512 + k0 + (tid&3)*8);
    };

    ldg_tile(0);
    for (int t = 0; t < ntile; t++){
        #pragma unroll
        for (int i=0;i<4;i++){
            int e = tid + i*256; int r = e>>3, c = (e&7)*4;
            *(uint2*)&As[r][c>>1] = make_uint2(pack2(ra[i].x, ra[i].y), pack2(ra[i].z, ra[i].w));
        }
        { int n = tid>>2, seg = (tid&3)*4; *(uint4*)&Bs[n][seg] = rbh; }
        __syncthreads();
        if (t+1 < ntile) ldg_tile(t+1);
        #pragma unroll
        for (int s=0; s<2; s++){
            int kp = s*8;
            uint32_t af[2][4];
            #pragma unroll
            for (int mi=0;mi<2;mi++){
                int rb_ = wm*32 + mi*16;
                af[mi][0]=As[rb_+g  ][kp+tg  ];
                af[mi][1]=As[rb_+g+8][kp+tg  ];
                af[mi][2]=As[rb_+g  ][kp+tg+4];
                af[mi][3]=As[rb_+g+8][kp+tg+4];
            }
            #pragma unroll
            for (int ni=0;ni<4;ni++){
                int cb = wn*32 + ni*8 + g;
                uint32_t b0=Bs[cb][kp+tg  ];
                uint32_t b1=Bs[cb][kp+tg+4];
                mma16(acc[0][ni], af[0][0],af[0][1],af[0][2],af[0][3], b0,b1);
                mma16(acc[1][ni], af[1][0],af[1][1],af[1][2],af[1][3], b0,b1);
            }
        }
        __syncthreads();
    }

    #pragma unroll
    for (int mi=0;mi<2;mi++)
        #pragma unroll
        for (int ni=0;ni<4;ni++)
            #pragma unroll
            for (int half=0; half<2; half++){
                int row = m0 + wm*32 + mi*16 + g + half*8;
                int col = n0 + wn*32 + ni*8 + tg*2;
                float b0v = bias1[col]   + (bias2 ? bias2[col]   : 0.f);
                float b1v = bias1[col+1] + (bias2 ? bias2[col+1] : 0.f);
                float v0 = acc[mi][ni][half*2+0] + b0v;
                float v1 = acc[mi][ni][half*2+1] + b1v;
                if (HALF_OUT){
                    int b = row >> 11, s = row & 2047;
                    int h = col >> 6,  d = col & 63;
                    size_t idx = (((size_t)(b*H_ + h))*S_ + s)*DEPTH + d;
                    *(uint32_t*)(Ch + idx) = pack2(v0, v1);
                } else {
                    *(float2*)(Cf + (size_t)row*512 + col) = make_float2(v0, v1);
                }
            }
}

// z=0: Q'  z=1: K''=k@Wk+pe@Wd  z=2: V'   (all fp16 head-split out)
__global__ __launch_bounds__(256)
void proj3(const float* q, const float* k, const float* pe, const float* v,
           const float* bq, const float* bk, const float* bv, const float* bd)
{
    __shared__ uint32_t As[128][20];
    __shared__ uint32_t Bs[64][20];
    int m0 = blockIdx.y*128, n0 = blockIdx.x*64;
    const __half* WqT = g_WT;
    const __half* WkT = g_WT + (size_t)512*512;
    const __half* WvT = g_WT + (size_t)2*512*512;
    const __half* WdT = g_WT + (size_t)3*512*512;
    if (blockIdx.z == 0)
        gemm16_core<1>(q, WqT, bq, nullptr,nullptr,nullptr, nullptr, g_Qh, m0,n0, As,Bs);
    else if (blockIdx.z == 1)
        gemm16_core<1>(k, WkT, bk, pe, WdT, bd, nullptr, g_Kh, m0,n0, As,Bs);
    else
        gemm16_core<1>(v, WvT, bv, nullptr,nullptr,nullptr, nullptr, g_Vh, m0,n0, As,Bs);
}

__global__ __launch_bounds__(256)
void gemm_out(const float* __restrict__ A, const float* __restrict__ bd, float* __restrict__ C)
{
    __shared__ uint32_t As[128][20];
    __shared__ uint32_t Bs[64][20];
    gemm16_core<0>(A, g_WT + (size_t)3*512*512, bd, nullptr,nullptr,nullptr, C, nullptr,
                   blockIdx.y*128, blockIdx.x*64, As, Bs);
}

// ---------------- pass 1: rowsum of exp(logits) ----------------
__global__ __launch_bounds__(256)
void attn_rowsum()
{
    extern __shared__ uint32_t sm1[];
    uint32_t (*Qs)[36] = (uint32_t(*)[36])sm1;                 // 128 x 32 k-pairs
    uint32_t (*Ks)[36] = (uint32_t(*)[36])(sm1 + 128*36);      // 64 x 32 d-pairs
    float *rs = (float*)(sm1 + 128*36 + 64*36);                // 128

    int tid = threadIdx.x;
    int lane = tid & 31, wid = tid >> 5;
    int g = lane >> 2, tg = lane & 3;
    int wm = wid & 3, wn = wid >> 2;
    int bh = blockIdx.y;
    int s0 = blockIdx.x * 128;

    const __half* qh = g_Qh + ((size_t)bh*S_ + s0)*DEPTH;
    const __half* kh = g_Kh +  (size_t)bh*S_*DEPTH;

    #pragma unroll
    for (int i=0;i<4;i++){
        int u = tid + i*256;
        int r = u>>3, c8 = u&7;
        *(uint4*)&Qs[r][c8*4] = *(const uint4*)(qh + (size_t)r*DEPTH + c8*8);
    }
    if (tid < 128) rs[tid] = 0.f;
    __syncthreads();

    uint4 kr[2];
    auto ldgK = [&](int t0){
        #pragma unroll
        for (int i=0;i<2;i++){
            int u = tid + i*256;
            int r = u>>3, c8 = u&7;
            kr[i] = *(const uint4*)(kh + (size_t)(t0+r)*DEPTH + c8*8);
        }
    };
    ldgK(0);

    float rowacc[4] = {0.f,0.f,0.f,0.f};

    for (int t0 = 0; t0 < S_; t0 += 64){
        #pragma unroll
        for (int i=0;i<2;i++){
            int u = tid + i*256;
            int r = u>>3, c8 = u&7;
            *(uint4*)&Ks[r][c8*4] = kr[i];
        }
        __syncthreads();
        if (t0 + 64 < S_) ldgK(t0 + 64);

        float acc[2][4][4];
        #pragma unroll
        for (int i=0;i<2;i++)
            #pragma unroll
            for (int j=0;j<4;j++)
                #pragma unroll
                for (int r=0;r<4;r++) acc[i][j][r]=0.f;

        #pragma unroll
        for (int s=0; s<4; s++){
            int kp = s*8;
            uint32_t af[2][4];
            #pragma unroll
            for (int mi=0;mi<2;mi++){
                int rb = wm*32 + mi*16;
                af[mi][0]=Qs[rb+g  ][kp+tg  ];
                af[mi][1]=Qs[rb+g+8][kp+tg  ];
                af[mi][2]=Qs[rb+g  ][kp+tg+4];
                af[mi][3]=Qs[rb+g+8][kp+tg+4];
            }
            #pragma unroll
            for (int ni=0;ni<4;ni++){
                int cb = wn*32 + ni*8 + g;
                uint32_t b0=Ks[cb][kp+tg  ];
                uint32_t b1=Ks[cb][kp+tg+4];
                mma16(acc[0][ni], af[0][0],af[0][1],af[0][2],af[0][3], b0,b1);
                mma16(acc[1][ni], af[1][0],af[1][1],af[1][2],af[1][3], b0,b1);
            }
        }
        #pragma unroll
        for (int mi=0;mi<2;mi++)
            #pragma unroll
            for (int ni=0;ni<4;ni++)
                #pragma unroll
                for (int r2=0;r2<4;r2++)
                    rowacc[mi*2 + (r2>>1)] += __expf(acc[mi][ni][r2]*0.125f);
        __syncthreads();
    }

    #pragma unroll
    for (int i=0;i<4;i++){
        float v = rowacc[i];
        v += __shfl_xor_sync(0xffffffffu, v, 1);
        v += __shfl_xor_sync(0xffffffffu, v, 2);
        if (tg == 0){
            int row = wm*32 + (i>>1)*16 + g + (i&1)*8;
            atomicAdd(&rs[row], v);
        }
    }
    __syncthreads();
    if (tid < 128) g_rsinv[(size_t)bh*S_ + s0 + tid] = 1.0f / rs[tid];
}

// ---------------- pass 2: attn write + ctx = attn @ V ----------------
__global__ __launch_bounds__(256)
void attn_pv(float* __restrict__ attn, float* __restrict__ ctx)
{
    extern __shared__ uint32_t sm2[];
    uint32_t (*Qs)[36] = (uint32_t(*)[36])sm2;                          // 128
    uint32_t (*Ks)[36] = (uint32_t(*)[36])(sm2 + 128*36);               // 64
    uint32_t (*Ps)[36] = (uint32_t(*)[36])(sm2 + 192*36);               // 128 (t-pairs)
    uint32_t (*Vs)[36] = (uint32_t(*)[36])(sm2 + 320*36);               // 64 d-rows (t-pairs)
    float *rsv = (float*)(sm2 + 384*36);                                // 128

    int tid = threadIdx.x;
    int lane = tid & 31, wid = tid >> 5;
    int g = lane >> 2, tg = lane & 3;
    int wm = wid & 3, wn = wid >> 2;
    int bh = blockIdx.y;
    int s0 = blockIdx.x * 128;

    const __half* qh = g_Qh + ((size_t)bh*S_ + s0)*DEPTH;
    const __half* kh = g_Kh +  (size_t)bh*S_*DEPTH;
    const __half* vt = g_Vt +  (size_t)bh*DEPTH*S_;
    float* attn_strip = attn + ((size_t)bh*S_ + s0)*S_;

    #pragma unroll
    for (int i=0;i<4;i++){
        int u = tid + i*256;
        int r = u>>3, c8 = u&7;
        *(uint4*)&Qs[r][c8*4] = *(const uint4*)(qh + (size_t)r*DEPTH + c8*8);
    }
    if (tid < 128) rsv[tid] = g_rsinv[(size_t)bh*S_ + s0 + tid];
    __syncthreads();

    uint4 kr[2], vr[2];
    auto ldgKV = [&](int t0){
        #pragma unroll
        for (int i=0;i<2;i++){
            int u = tid + i*256;
            int r = u>>3, c8 = u&7;
            kr[i] = *(const uint4*)(kh + (size_t)(t0+r)*DEPTH + c8*8);
            vr[i] = *(const uint4*)(vt + (size_t)r*S_ + t0 + c8*8);    // r = d
        }
    };
    ldgKV(0);

    float octx[2][4][4];
    #pragma unroll
    for (int i=0;i<2;i++)
        #pragma unroll
        for (int j=0;j<4;j++)
            #pragma unroll
            for (int r=0;r<4;r++) octx[i][j][r]=0.f;

    for (int t0 = 0; t0 < S_; t0 += 64){
        #pragma unroll
        for (int i=0;i<2;i++){
            int u = tid + i*256;
            int r = u>>3, c8 = u&7;
            *(uint4*)&Ks[r][c8*4] = kr[i];
            *(uint4*)&Vs[r][c8*4] = vr[i];
        }
        __syncthreads();
        if (t0 + 64 < S_) ldgKV(t0 + 64);

        float acc[2][4][4];
        #pragma unroll
        for (int i=0;i<2;i++)
            #pragma unroll
            for (int j=0;j<4;j++)
                #pragma unroll
                for (int r=0;r<4;r++) acc[i][j][r]=0.f;

        // logits = Q @ K''^T
        #pragma unroll
        for (int s=0; s<4; s++){
            int kp = s*8;
            uint32_t af[2][4];
            #pragma unroll
            for (int mi=0;mi<2;mi++){
                int rb = wm*32 + mi*16;
                af[mi][0]=Qs[rb+g  ][kp+tg  ];
                af[mi][1]=Qs[rb+g+8][kp+tg  ];
                af[mi][2]=Qs[rb+g  ][kp+tg+4];
                af[mi][3]=Qs[rb+g+8][kp+tg+4];
            }
            #pragma unroll
            for (int ni=0;ni<4;ni++){
                int cb = wn*32 + ni*8 + g;
                uint32_t b0=Ks[cb][kp+tg  ];
                uint32_t b1=Ks[cb][kp+tg+4];
                mma16(acc[0][ni], af[0][0],af[0][1],af[0][2],af[0][3], b0,b1);
                mma16(acc[1][ni], af[1][0],af[1][1],af[1][2],af[1][3], b0,b1);
            }
        }

        // p = exp(l/8)*inv ; write attn fp32 + stage P fp16 (t-pairs)
        #pragma unroll
        for (int mi=0;mi<2;mi++){
            int r0 = wm*32 + mi*16 + g;
            float inv0 = rsv[r0], inv1 = rsv[r0+8];
            #pragma unroll
            for (int ni=0;ni<4;ni++){
                acc[mi][ni][0] = __expf(acc[mi][ni][0]*0.125f)*inv0;
                acc[mi][ni][1] = __expf(acc[mi][ni][1]*0.125f)*inv0;
                acc[mi][ni][2] = __expf(acc[mi][ni][2]*0.125f)*inv1;
                acc[mi][ni][3] = __expf(acc[mi][ni][3]*0.125f)*inv1;
            }
        }
        #pragma unroll
        for (int mi=0;mi<2;mi++)
            #pragma unroll
            for (int ni=0;ni<4;ni++)
                #pragma unroll
                for (int half=0; half<2; half++){
                    int rloc = wm*32 + mi*16 + g + half*8;
                    int cloc = wn*32 + ni*8 + tg*2;
                    float v0 = acc[mi][ni][half*2], v1 = acc[mi][ni][half*2+1];
                    Ps[rloc][wn*16 + ni*4 + tg] = pack2(v0, v1);
                    *(float2*)(attn_strip + (size_t)rloc*S_ + t0 + cloc) = make_float2(v0, v1);
                }
        __syncthreads();   // P,V ready before PV mma

        // ctx += P @ V
        #pragma unroll
        for (int s=0; s<4; s++){
            int kp = s*8;
            uint32_t af[2][4];
            #pragma unroll
            for (int mi=0;mi<2;mi++){
                int rb = wm*32 + mi*16;
                af[mi][0]=Ps[rb+g  ][kp+tg  ];
                af[mi][1]=Ps[rb+g+8][kp+tg  ];
                af[mi][2]=Ps[rb+g  ][kp+tg+4];
                af[mi][3]=Ps[rb+g+8][kp+tg+4];
            }
            #pragma unroll
            for (int ni=0;ni<4;ni++){
                int cb = wn*32 + ni*8 + g;       // d index
                uint32_t b0=Vs[cb][kp+tg  ];
                uint32_t b1=Vs[cb][kp+tg+4];
                mma16(octx[0][ni], af[0][0],af[0][1],af[0][2],af[0][3], b0,b1);
                mma16(octx[1][ni], af[1][0],af[1][1],af[1][2],af[1][3], b0,b1);
            }
        }
        __syncthreads();   // before Ks/Vs/Ps overwritten
    }

    // write ctx in (B,S,D) layout
    int b = bh >> 3, h = bh & 7;
    #pragma unroll
    for (int mi=0;mi<2;mi++)
        #pragma unroll
        for (int ni=0;ni<4;ni++)
            #pragma unroll
            for (int half=0; half<2; half++){
                int row = s0 + wm*32 + mi*16 + g + half*8;
                int col = h*64 + wn*32 + ni*8 + tg*2;
                float2 v2 = make_float2(octx[mi][ni][half*2], octx[mi][ni][half*2+1]);
                *(float2*)(ctx + ((size_t)b*S_ + row)*D_ + col) = v2;
            }
}

// ---------------- launch ----------------
extern "C" void kernel_launch(void* const* d_in, const int* in_sizes, int n_in,
                              void* d_out, int out_size)
{
    const float* q   = (const float*)d_in[0];
    const float* k   = (const float*)d_in[1];
    const float* v   = (const float*)d_in[2];
    const float* pe  = (const float*)d_in[3];
    // d_in[4] = mask (unused by reference)
    const float* Wq  = (const float*)d_in[5];
    const float* bq  = (const float*)d_in[6];
    const float* Wk  = (const float*)d_in[7];
    const float* bk  = (const float*)d_in[8];
    const float* Wv  = (const float*)d_in[9];
    const float* bv  = (const float*)d_in[10];
    const float* Wd  = (const float*)d_in[11];
    const float* bd  = (const float*)d_in[12];

    float* out  = (float*)d_out;                       // (B,S,D)
    float* attn = out + (size_t)B_*S_*D_;              // (B,H,S,S)

    float* Ctx;
    cudaGetSymbolAddress((void**)&Ctx, g_ctx);

    transW<<<dim3(8, 8, 4), 256>>>(Wq, Wk, Wv, Wd);
    proj3<<<dim3(8, 64, 3), 256>>>(q, k, pe, v, bq, bk, bv, bd);
    transV<<<dim3(S_/64, BH), 256>>>();

    size_t smA = (size_t)(128*36 + 64*36)*sizeof(uint32_t) + 128*sizeof(float);
    cudaFuncSetAttribute(attn_rowsum, cudaFuncAttributeMaxDynamicSharedMemorySize, (int)smA);
    attn_rowsum<<<dim3(16, BH), 256, smA>>>();

    size_t smB = (size_t)(384*36)*sizeof(uint32_t) + 128*sizeof(float);
    cudaFuncSetAttribute(attn_pv, cudaFuncAttributeMaxDynamicSharedMemorySize, (int)smB);
    attn_pv<<<dim3(16, BH), 256, smB>>>(attn, Ctx);

    gemm_out<<<dim3(8, 64), 256>>>(Ctx, bd, out);
}

// round 10
// speedup vs baseline: 2.1117x; 1.0806x over previous
#include <cuda_runtime.h>
#include <cuda_fp16.h>
#include <cstdint>
#include <cstddef>

#define B_  4
#define S_  2048
#define D_  512
#define H_  8
#define DEPTH 64
#define BH  (B_*H_)

#define QSCALE 0.1803368801111832f   // log2(e)/8

// ---------------- scratch ----------------
__device__ __half g_WT[(size_t)4*512*512];      // W^T fp16 [which][n][k]
__device__ __half g_Qh[(size_t)BH*S_*DEPTH];    // Q'·log2e/8 fp16 head-split
__device__ __half g_Kh[(size_t)BH*S_*DEPTH];    // K'' fp16 head-split
__device__ __half g_Vh[(size_t)BH*S_*DEPTH];    // V'  fp16 head-split
__device__ __half g_Vt[(size_t)BH*DEPTH*S_];    // V'^T fp16 (bh,d,t)
__device__ float  g_ctx[(size_t)B_*S_*D_];
__device__ float  g_rsinv[(size_t)BH*S_];

// ---------------- helpers ----------------
__device__ __forceinline__ uint32_t pack2(float a, float b){
    __half2 h = __floats2half2_rn(a, b);
    return *(uint32_t*)&h;
}
__device__ __forceinline__ float ex2f(float x){
    float y; asm("ex2.approx.ftz.f32 %0, %1;" : "=f"(y) : "f"(x)); return y;
}
__device__ __forceinline__ uint32_t s2u(const void* p){
    uint32_t r; asm("{ .reg .u64 t; cvta.to.shared.u64 t, %1; cvt.u32.u64 %0, t; }"
                    : "=r"(r) : "l"(p)); return r;
}
__device__ __forceinline__ void mma16(float c[4], uint32_t a0,uint32_t a1,uint32_t a2,uint32_t a3,
                                      uint32_t b0,uint32_t b1){
    asm volatile("mma.sync.aligned.m16n8k16.row.col.f32.f16.f16.f32 "
        "{%0,%1,%2,%3}, {%4,%5,%6,%7}, {%8,%9}, {%0,%1,%2,%3};"
        : "+f"(c[0]),"+f"(c[1]),"+f"(c[2]),"+f"(c[3])
        : "r"(a0),"r"(a1),"r"(a2),"r"(a3),"r"(b0),"r"(b1));
}
__device__ __forceinline__ void ldsm4(uint32_t &r0,uint32_t &r1,uint32_t &r2,uint32_t &r3,
                                      uint32_t addr){
    asm volatile("ldmatrix.sync.aligned.m8n8.x4.shared.b16 {%0,%1,%2,%3}, [%4];"
        : "=r"(r0),"=r"(r1),"=r"(r2),"=r"(r3) : "r"(addr));
}

// A-operand ldmatrix address offset for lane l (row-major [row][k-pair], stride SW u32):
//   m0: row+(l&7), kp ; m1: row+8+(l&7), kp ; m2: row+(l&7), kp+4 ; m3: row+8+(l&7), kp+4
#define A_LANE_OFF(l, SW) (((((l)&7) + (((l)>>3)&1)*8) * (SW) + (((l)>>4)&1)*4) * 4)
// B-operand x4 covering two n8 blocks (rows = n, stride SW):
//   m0: n+(l&7), kp ; m1: n+(l&7), kp+4 ; m2: n+8+(l&7), kp ; m3: n+8+(l&7), kp+4
#define B_LANE_OFF(l, SW) (((((l)&7) + (((l)>>4)&1)*8) * (SW) + (((l)>>3)&1)*4) * 4)

// ---------------- W transpose + fp16 convert ----------------
__global__ __launch_bounds__(256)
void transW(const float* Wq, const float* Wk, const float* Wv, const float* Wd)
{
    __shared__ float ts[64][65];
    const float* W = (blockIdx.z==0)?Wq:(blockIdx.z==1)?Wk:(blockIdx.z==2)?Wv:Wd;
    __half* WT = g_WT + (size_t)blockIdx.z*512*512;
    int k0 = blockIdx.y*64, n0 = blockIdx.x*64;
    int tid = threadIdx.x;
    #pragma unroll
    for (int i=0;i<4;i++){
        int e = tid + i*256;
        int r = e>>4, c = (e&15)*4;
        float4 x = *(const float4*)(W + (size_t)(k0+r)*512 + n0 + c);
        ts[r][c]=x.x; ts[r][c+1]=x.y; ts[r][c+2]=x.z; ts[r][c+3]=x.w;
    }
    __syncthreads();
    #pragma unroll
    for (int i=0;i<2;i++){
        int u = tid + i*256;
        int n = u>>3, seg = (u&7)*8;
        uint32_t h[4];
        #pragma unroll
        for (int j=0;j<4;j++)
            h[j] = pack2(ts[seg+2*j][n], ts[seg+2*j+1][n]);
        *(uint4*)(WT + (size_t)(n0+n)*512 + k0 + seg) = make_uint4(h[0],h[1],h[2],h[3]);
    }
}

// ---------------- V transpose ----------------
__global__ __launch_bounds__(256)
void transV()
{
    __shared__ __half ts[64][72];
    int tid = threadIdx.x;
    int bh = blockIdx.y, t0 = blockIdx.x*64;
    const __half* src = g_Vh + ((size_t)bh*S_ + t0)*DEPTH;
    #pragma unroll
    for (int i=0;i<2;i++){
        int u = tid + i*256;
        int r = u>>3, c = (u&7)*8;
        *(uint4*)&ts[r][c] = *(const uint4*)(src + (size_t)r*DEPTH + c);
    }
    __syncthreads();
    #pragma unroll
    for (int i=0;i<2;i++){
        int u = tid + i*256;
        int d = u>>3, seg = (u&7)*8;
        __half h[8];
        #pragma unroll
        for (int j=0;j<8;j++) h[j] = ts[seg+j][d];
        *(uint4*)(g_Vt + ((size_t)bh*DEPTH + d)*S_ + t0 + seg) = *(uint4*)h;
    }
}

// ---------------- fp16 GEMM core ----------------
template<int HALF_OUT>
__device__ __forceinline__ void gemm16_core(
    const float* __restrict__ A1, const __half* __restrict__ BT1, const float* __restrict__ bias1,
    const float* __restrict__ A2, const __half* __restrict__ BT2, const float* __restrict__ bias2,
    float* __restrict__ Cf, __half* __restrict__ Ch, int m0, int n0, float oscale,
    uint32_t (*As)[20], uint32_t (*Bs)[20])
{
    int tid = threadIdx.x;
    int lane = tid & 31, wid = tid >> 5;
    int g = lane >> 2, tg = lane & 3;
    int wm = wid & 3, wn = wid >> 2;          // 4x2 warps -> CTA tile 128x64

    float acc[2][4][4];
    #pragma unroll
    for (int i=0;i<2;i++)
        #pragma unroll
        for (int j=0;j<4;j++)
            #pragma unroll
            for (int r=0;r<4;r++) acc[i][j][r]=0.f;

    uint32_t aAddr = s2u(&As[0][0]) + (uint32_t)(wm*32*20*4) + A_LANE_OFF(lane, 20);
    uint32_t bAddr = s2u(&Bs[0][0]) + (uint32_t)(wn*32*20*4) + B_LANE_OFF(lane, 20);

    const int ntile = A2 ? 32 : 16;
    float4 ra[4]; uint4 rbh;
    auto ldg_tile = [&](int t){
        const float* A   = (t >= 16) ? A2  : A1;
        const __half* BT = (t >= 16) ? BT2 : BT1;
        int k0 = (t & 15) * 32;
        #pragma unroll
        for (int i=0;i<4;i++){
            int e = tid + i*256; int r = e>>3, c = (e&7)*4;
            ra[i] = *(const float4*)(A + (size_t)(m0+r)*512 + k0 + c);
        }
        rbh = *(const uint4*)(BT + (size_t)(n0 + (tid>>2))*512 + k0 + (tid&3)*8);
    };

    ldg_tile(0);
    for (int t = 0; t < ntile; t++){
        #pragma unroll
        for (int i=0;i<4;i++){
            int e = tid + i*256; int r = e>>3, c = (e&7)*4;
            *(uint2*)&As[r][c>>1] = make_uint2(pack2(ra[i].x, ra[i].y), pack2(ra[i].z, ra[i].w));
        }
        { int n = tid>>2, seg = (tid&3)*4; *(uint4*)&Bs[n][seg] = rbh; }
        __syncthreads();
        if (t+1 < ntile) ldg_tile(t+1);
        #pragma unroll
        for (int s=0; s<2; s++){
            uint32_t koff = (uint32_t)(s*32);     // 8 u32 slots
            uint32_t a0[4], a1[4], b0[4], b1[4];
            ldsm4(a0[0],a0[1],a0[2],a0[3], aAddr + koff);
            ldsm4(a1[0],a1[1],a1[2],a1[3], aAddr + (uint32_t)(16*20*4) + koff);
            ldsm4(b0[0],b0[1],b0[2],b0[3], bAddr + koff);
            ldsm4(b1[0],b1[1],b1[2],b1[3], bAddr + (uint32_t)(16*20*4) + koff);
            mma16(acc[0][0], a0[0],a0[1],a0[2],a0[3], b0[0],b0[1]);
            mma16(acc[0][1], a0[0],a0[1],a0[2],a0[3], b0[2],b0[3]);
            mma16(acc[0][2], a0[0],a0[1],a0[2],a0[3], b1[0],b1[1]);
            mma16(acc[0][3], a0[0],a0[1],a0[2],a0[3], b1[2],b1[3]);
            mma16(acc[1][0], a1[0],a1[1],a1[2],a1[3], b0[0],b0[1]);
            mma16(acc[1][1], a1[0],a1[1],a1[2],a1[3], b0[2],b0[3]);
            mma16(acc[1][2], a1[0],a1[1],a1[2],a1[3], b1[0],b1[1]);
            mma16(acc[1][3], a1[0],a1[1],a1[2],a1[3], b1[2],b1[3]);
        }
        __syncthreads();
    }

    #pragma unroll
    for (int mi=0;mi<2;mi++)
        #pragma unroll
        for (int ni=0;ni<4;ni++)
            #pragma unroll
            for (int half=0; half<2; half++){
                int row = m0 + wm*32 + mi*16 + g + half*8;
                int col = n0 + wn*32 + ni*8 + tg*2;
                float b0v = bias1[col]   + (bias2 ? bias2[col]   : 0.f);
                float b1v = bias1[col+1] + (bias2 ? bias2[col+1] : 0.f);
                float v0 = (acc[mi][ni][half*2+0] + b0v) * oscale;
                float v1 = (acc[mi][ni][half*2+1] + b1v) * oscale;
                if (HALF_OUT){
                    int b = row >> 11, s = row & 2047;
                    int h = col >> 6,  d = col & 63;
                    size_t idx = (((size_t)(b*H_ + h))*S_ + s)*DEPTH + d;
                    *(uint32_t*)(Ch + idx) = pack2(v0, v1);
                } else {
                    *(float2*)(Cf + (size_t)row*512 + col) = make_float2(v0, v1);
                }
            }
}

// z=0: Q'·log2e/8  z=1: K''  z=2: V'
__global__ __launch_bounds__(256)
void proj3(const float* q, const float* k, const float* pe, const float* v,
           const float* bq, const float* bk, const float* bv, const float* bd)
{
    __shared__ uint32_t As[128][20];
    __shared__ uint32_t Bs[64][20];
    int m0 = blockIdx.y*128, n0 = blockIdx.x*64;
    const __half* WqT = g_WT;
    const __half* WkT = g_WT + (size_t)512*512;
    const __half* WvT = g_WT + (size_t)2*512*512;
    const __half* WdT = g_WT + (size_t)3*512*512;
    if (blockIdx.z == 0)
        gemm16_core<1>(q, WqT, bq, nullptr,nullptr,nullptr, nullptr, g_Qh, m0,n0, QSCALE, As,Bs);
    else if (blockIdx.z == 1)
        gemm16_core<1>(k, WkT, bk, pe, WdT, bd, nullptr, g_Kh, m0,n0, 1.f, As,Bs);
    else
        gemm16_core<1>(v, WvT, bv, nullptr,nullptr,nullptr, nullptr, g_Vh, m0,n0, 1.f, As,Bs);
}

__global__ __launch_bounds__(256)
void gemm_out(const float* __restrict__ A, const float* __restrict__ bd, float* __restrict__ C)
{
    __shared__ uint32_t As[128][20];
    __shared__ uint32_t Bs[64][20];
    gemm16_core<0>(A, g_WT + (size_t)3*512*512, bd, nullptr,nullptr,nullptr, C, nullptr,
                   blockIdx.y*128, blockIdx.x*64, 1.f, As, Bs);
}

// ---------------- pass 1: rowsum of exp(logits) ----------------
__global__ __launch_bounds__(256)
void attn_rowsum()
{
    extern __shared__ uint32_t sm1[];
    uint32_t (*Qs)[36] = (uint32_t(*)[36])sm1;                 // 128 rows
    uint32_t (*Ks)[36] = (uint32_t(*)[36])(sm1 + 128*36);      // 64 rows
    float *rs = (float*)(sm1 + 128*36 + 64*36);                // 128

    int tid = threadIdx.x;
    int lane = tid & 31, wid = tid >> 5;
    int g = lane >> 2, tg = lane & 3;
    int wm = wid & 3, wn = wid >> 2;
    int bh = blockIdx.y;
    int s0 = blockIdx.x * 128;

    const __half* qh = g_Qh + ((size_t)bh*S_ + s0)*DEPTH;
    const __half* kh = g_Kh +  (size_t)bh*S_*DEPTH;

    uint32_t qAddr = s2u(&Qs[0][0]) + (uint32_t)(wm*32*36*4) + A_LANE_OFF(lane, 36);
    uint32_t kAddr = s2u(&Ks[0][0]) + (uint32_t)(wn*32*36*4) + B_LANE_OFF(lane, 36);

    #pragma unroll
    for (int i=0;i<4;i++){
        int u = tid + i*256;
        int r = u>>3, c8 = u&7;
        *(uint4*)&Qs[r][c8*4] = *(const uint4*)(qh + (size_t)r*DEPTH + c8*8);
    }
    if (tid < 128) rs[tid] = 0.f;
    __syncthreads();

    uint4 kr[2];
    auto ldgK = [&](int t0){
        #pragma unroll
        for (int i=0;i<2;i++){
            int u = tid + i*256;
            int r = u>>3, c8 = u&7;
            kr[i] = *(const uint4*)(kh + (size_t)(t0+r)*DEPTH + c8*8);
        }
    };
    ldgK(0);

    float rowacc[4] = {0.f,0.f,0.f,0.f};

    for (int t0 = 0; t0 < S_; t0 += 64){
        #pragma unroll
        for (int i=0;i<2;i++){
            int u = tid + i*256;
            int r = u>>3, c8 = u&7;
            *(uint4*)&Ks[r][c8*4] = kr[i];
        }
        __syncthreads();
        if (t0 + 64 < S_) ldgK(t0 + 64);

        float acc[2][4][4];
        #pragma unroll
        for (int i=0;i<2;i++)
            #pragma unroll
            for (int j=0;j<4;j++)
                #pragma unroll
                for (int r=0;r<4;r++) acc[i][j][r]=0.f;

        #pragma unroll
        for (int s=0; s<4; s++){
            uint32_t koff = (uint32_t)(s*32);
            uint32_t a0[4], a1[4], b0[4], b1[4];
            ldsm4(a0[0],a0[1],a0[2],a0[3], qAddr + koff);
            ldsm4(a1[0],a1[1],a1[2],a1[3], qAddr + (uint32_t)(16*36*4) + koff);
            ldsm4(b0[0],b0[1],b0[2],b0[3], kAddr + koff);
            ldsm4(b1[0],b1[1],b1[2],b1[3], kAddr + (uint32_t)(16*36*4) + koff);
            mma16(acc[0][0], a0[0],a0[1],a0[2],a0[3], b0[0],b0[1]);
            mma16(acc[0][1], a0[0],a0[1],a0[2],a0[3], b0[2],b0[3]);
            mma16(acc[0][2], a0[0],a0[1],a0[2],a0[3], b1[0],b1[1]);
            mma16(acc[0][3], a0[0],a0[1],a0[2],a0[3], b1[2],b1[3]);
            mma16(acc[1][0], a1[0],a1[1],a1[2],a1[3], b0[0],b0[1]);
            mma16(acc[1][1], a1[0],a1[1],a1[2],a1[3], b0[2],b0[3]);
            mma16(acc[1][2], a1[0],a1[1],a1[2],a1[3], b1[0],b1[1]);
            mma16(acc[1][3], a1[0],a1[1],a1[2],a1[3], b1[2],b1[3]);
        }
        #pragma unroll
        for (int mi=0;mi<2;mi++)
            #pragma unroll
            for (int ni=0;ni<4;ni++)
                #pragma unroll
                for (int r2=0;r2<4;r2++)
                    rowacc[mi*2 + (r2>>1)] += ex2f(acc[mi][ni][r2]);
        __syncthreads();
    }

    #pragma unroll
    for (int i=0;i<4;i++){
        float v = rowacc[i];
        v += __shfl_xor_sync(0xffffffffu, v, 1);
        v += __shfl_xor_sync(0xffffffffu, v, 2);
        if (tg == 0){
            int row = wm*32 + (i>>1)*16 + g + (i&1)*8;
            atomicAdd(&rs[row], v);
        }
    }
    __syncthreads();
    if (tid < 128) g_rsinv[(size_t)bh*S_ + s0 + tid] = 1.0f / rs[tid];
}

// ---------------- pass 2: attn write + ctx = attn @ V ----------------
__global__ __launch_bounds__(256)
void attn_pv(float* __restrict__ attn, float* __restrict__ ctx)
{
    extern __shared__ uint32_t sm2[];
    uint32_t (*Qs)[36] = (uint32_t(*)[36])sm2;                          // 128
    uint32_t (*Ks)[36] = (uint32_t(*)[36])(sm2 + 128*36);               // 64
    uint32_t (*Ps)[36] = (uint32_t(*)[36])(sm2 + 192*36);               // 128 (t-pairs)
    uint32_t (*Vs)[36] = (uint32_t(*)[36])(sm2 + 320*36);               // 64 d-rows (t-pairs)
    float *rsv = (float*)(sm2 + 384*36);                                // 128

    int tid = threadIdx.x;
    int lane = tid & 31, wid = tid >> 5;
    int g = lane >> 2, tg = lane & 3;
    int wm = wid & 3, wn = wid >> 2;
    int bh = blockIdx.y;
    int s0 = blockIdx.x * 128;

    const __half* qh = g_Qh + ((size_t)bh*S_ + s0)*DEPTH;
    const __half* kh = g_Kh +  (size_t)bh*S_*DEPTH;
    const __half* vt = g_Vt +  (size_t)bh*DEPTH*S_;
    float* attn_strip = attn + ((size_t)bh*S_ + s0)*S_;

    uint32_t qAddr = s2u(&Qs[0][0]) + (uint32_t)(wm*32*36*4) + A_LANE_OFF(lane, 36);
    uint32_t kAddr = s2u(&Ks[0][0]) + (uint32_t)(wn*32*36*4) + B_LANE_OFF(lane, 36);
    uint32_t pAddr = s2u(&Ps[0][0]) + (uint32_t)(wm*32*36*4) + A_LANE_OFF(lane, 36);
    uint32_t vAddr = s2u(&Vs[0][0]) + (uint32_t)(wn*32*36*4) + B_LANE_OFF(lane, 36);

    #pragma unroll
    for (int i=0;i<4;i++){
        int u = tid + i*256;
        int r = u>>3, c8 = u&7;
        *(uint4*)&Qs[r][c8*4] = *(const uint4*)(qh + (size_t)r*DEPTH + c8*8);
    }
    if (tid < 128) rsv[tid] = g_rsinv[(size_t)bh*S_ + s0 + tid];
    __syncthreads();

    uint4 kr[2], vr[2];
    auto ldgKV = [&](int t0){
        #pragma unroll
        for (int i=0;i<2;i++){
            int u = tid + i*256;
            int r = u>>3, c8 = u&7;
            kr[i] = *(const uint4*)(kh + (size_t)(t0+r)*DEPTH + c8*8);
            vr[i] = *(const uint4*)(vt + (size_t)r*S_ + t0 + c8*8);    // r = d
        }
    };
    ldgKV(0);

    float octx[2][4][4];
    #pragma unroll
    for (int i=0;i<2;i++)
        #pragma unroll
        for (int j=0;j<4;j++)
            #pragma unroll
            for (int r=0;r<4;r++) octx[i][j][r]=0.f;

    for (int t0 = 0; t0 < S_; t0 += 64){
        #pragma unroll
        for (int i=0;i<2;i++){
            int u = tid + i*256;
            int r = u>>3, c8 = u&7;
            *(uint4*)&Ks[r][c8*4] = kr[i];
            *(uint4*)&Vs[r][c8*4] = vr[i];
        }
        __syncthreads();
        if (t0 + 64 < S_) ldgKV(t0 + 64);

        float acc[2][4][4];
        #pragma unroll
        for (int i=0;i<2;i++)
            #pragma unroll
            for (int j=0;j<4;j++)
                #pragma unroll
                for (int r=0;r<4;r++) acc[i][j][r]=0.f;

        // logits·log2e/8 = Q @ K''^T
        #pragma unroll
        for (int s=0; s<4; s++){
            uint32_t koff = (uint32_t)(s*32);
            uint32_t a0[4], a1[4], b0[4], b1[4];
            ldsm4(a0[0],a0[1],a0[2],a0[3], qAddr + koff);
            ldsm4(a1[0],a1[1],a1[2],a1[3], qAddr + (uint32_t)(16*36*4) + koff);
            ldsm4(b0[0],b0[1],b0[2],b0[3], kAddr + koff);
            ldsm4(b1[0],b1[1],b1[2],b1[3], kAddr + (uint32_t)(16*36*4) + koff);
            mma16(acc[0][0], a0[0],a0[1],a0[2],a0[3], b0[0],b0[1]);
            mma16(acc[0][1], a0[0],a0[1],a0[2],a0[3], b0[2],b0[3]);
            mma16(acc[0][2], a0[0],a0[1],a0[2],a0[3], b1[0],b1[1]);
            mma16(acc[0][3], a0[0],a0[1],a0[2],a0[3], b1[2],b1[3]);
            mma16(acc[1][0], a1[0],a1[1],a1[2],a1[3], b0[0],b0[1]);
            mma16(acc[1][1], a1[0],a1[1],a1[2],a1[3], b0[2],b0[3]);
            mma16(acc[1][2], a1[0],a1[1],a1[2],a1[3], b1[0],b1[1]);
            mma16(acc[1][3], a1[0],a1[1],a1[2],a1[3], b1[2],b1[3]);
        }

        // p = 2^acc * inv ; write attn fp32 + stage P fp16 (t-pairs)
        #pragma unroll
        for (int mi=0;mi<2;mi++){
            int r0 = wm*32 + mi*16 + g;
            float inv0 = rsv[r0], inv1 = rsv[r0+8];
            #pragma unroll
            for (int ni=0;ni<4;ni++){
                acc[mi][ni][0] = ex2f(acc[mi][ni][0])*inv0;
                acc[mi][ni][1] = ex2f(acc[mi][ni][1])*inv0;
                acc[mi][ni][2] = ex2f(acc[mi][ni][2])*inv1;
                acc[mi][ni][3] = ex2f(acc[mi][ni][3])*inv1;
            }
        }
        #pragma unroll
        for (int mi=0;mi<2;mi++)
            #pragma unroll
            for (int ni=0;ni<4;ni++)
                #pragma unroll
                for (int half=0; half<2; half++){
                    int rloc = wm*32 + mi*16 + g + half*8;
                    int cloc = wn*32 + ni*8 + tg*2;
                    float v0 = acc[mi][ni][half*2], v1 = acc[mi][ni][half*2+1];
                    Ps[rloc][wn*16 + ni*4 + tg] = pack2(v0, v1);
                    *(float2*)(attn_strip + (size_t)rloc*S_ + t0 + cloc) = make_float2(v0, v1);
                }
        __syncthreads();   // P,V ready before PV mma

        // ctx += P @ V
        #pragma unroll
        for (int s=0; s<4; s++){
            uint32_t koff = (uint32_t)(s*32);
            uint32_t a0[4], a1[4], b0[4], b1[4];
            ldsm4(a0[0],a0[1],a0[2],a0[3], pAddr + koff);
            ldsm4(a1[0],a1[1],a1[2],a1[3], pAddr + (uint32_t)(16*36*4) + koff);
            ldsm4(b0[0],b0[1],b0[2],b0[3], vAddr + koff);
            ldsm4(b1[0],b1[1],b1[2],b1[3], vAddr + (uint32_t)(16*36*4) + koff);
            mma16(octx[0][0], a0[0],a0[1],a0[2],a0[3], b0[0],b0[1]);
            mma16(octx[0][1], a0[0],a0[1],a0[2],a0[3], b0[2],b0[3]);
            mma16(octx[0][2], a0[0],a0[1],a0[2],a0[3], b1[0],b1[1]);
            mma16(octx[0][3], a0[0],a0[1],a0[2],a0[3], b1[2],b1[3]);
            mma16(octx[1][0], a1[0],a1[1],a1[2],a1[3], b0[0],b0[1]);
            mma16(octx[1][1], a1[0],a1[1],a1[2],a1[3], b0[2],b0[3]);
            mma16(octx[1][2], a1[0],a1[1],a1[2],a1[3], b1[0],b1[1]);
            mma16(octx[1][3], a1[0],a1[1],a1[2],a1[3], b1[2],b1[3]);
        }
        __syncthreads();   // before Ks/Vs/Ps overwritten
    }

    // write ctx in (B,S,D) layout
    int b = bh >> 3, h = bh & 7;
    #pragma unroll
    for (int mi=0;mi<2;mi++)
        #pragma unroll
        for (int ni=0;ni<4;ni++)
            #pragma unroll
            for (int half=0; half<2; half++){
                int row = s0 + wm*32 + mi*16 + g + half*8;
                int col = h*64 + wn*32 + ni*8 + tg*2;
                float2 v2 = make_float2(octx[mi][ni][half*2], octx[mi][ni][half*2+1]);
                *(float2*)(ctx + ((size_t)b*S_ + row)*D_ + col) = v2;
            }
}

// ---------------- launch ----------------
extern "C" void kernel_launch(void* const* d_in, const int* in_sizes, int n_in,
                              void* d_out, int out_size)
{
    const float* q   = (const float*)d_in[0];
    const float* k   = (const float*)d_in[1];
    const float* v   = (const float*)d_in[2];
    const float* pe  = (const float*)d_in[3];
    // d_in[4] = mask (unused by reference)
    const float* Wq  = (const float*)d_in[5];
    const float* bq  = (const float*)d_in[6];
    const float* Wk  = (const float*)d_in[7];
    const float* bk  = (const float*)d_in[8];
    const float* Wv  = (const float*)d_in[9];
    const float* bv  = (const float*)d_in[10];
    const float* Wd  = (const float*)d_in[11];
    const float* bd  = (const float*)d_in[12];

    float* out  = (float*)d_out;                       // (B,S,D)
    float* attn = out + (size_t)B_*S_*D_;              // (B,H,S,S)

    float* Ctx;
    cudaGetSymbolAddress((void**)&Ctx, g_ctx);

    transW<<<dim3(8, 8, 4), 256>>>(Wq, Wk, Wv, Wd);
    proj3<<<dim3(8, 64, 3), 256>>>(q, k, pe, v, bq, bk, bv, bd);
    transV<<<dim3(S_/64, BH), 256>>>();

    size_t smA = (size_t)(128*36 + 64*36)*sizeof(uint32_t) + 128*sizeof(float);
    cudaFuncSetAttribute(attn_rowsum, cudaFuncAttributeMaxDynamicSharedMemorySize, (int)smA);
    attn_rowsum<<<dim3(16, BH), 256, smA>>>();

    size_t smB = (size_t)(384*36)*sizeof(uint32_t) + 128*sizeof(float);
    cudaFuncSetAttribute(attn_pv, cudaFuncAttributeMaxDynamicSharedMemorySize, (int)smB);
    attn_pv<<<dim3(16, BH), 256, smB>>>(attn, Ctx);

    gemm_out<<<dim3(8, 64), 256>>>(Ctx, bd, out);
}